// round 5
// baseline (speedup 1.0000x reference)
#include <cuda_runtime.h>
#include <cuda_bf16.h>
#include <stdint.h>

#define T_LEN 1024
#define NTH   256

// ---- smem byte layout ----
#define OFF_MASK 0                 // 2 buffers x 512B
#define OFF_STG  1024              // 64*132 f32 staging (33792B), reused for O out
#define OFF_K0   34816             // K buf p: HI at +0, LO at +16384 (32KB/buf)
#define OFF_V0   100352            // V buf p: HI at +0, LO at +16384
#define OFF_QHI  165888            // [t=128][c=64] bf16 SW128, 16KB
#define OFF_QLO  182272
#define SMEM_BYTES 198656

#define SWZ(o) ((o) ^ (((o) >> 3) & 0x70))

typedef uint32_t u32;

__device__ __forceinline__ u32 smem_u32(const void* p) {
    u32 a;
    asm("{ .reg .u64 t; cvta.to.shared.u64 t, %1; cvt.u32.u64 %0, t; }"
        : "=r"(a) : "l"(p));
    return a;
}
// pack (a,b) -> bf16x2 (a in lo)
__device__ __forceinline__ u32 pkbf(float a, float b) {
    u32 r;
    asm("cvt.rn.satfinite.bf16x2.f32 %0, %1, %2;" : "=r"(r) : "f"(b), "f"(a));
    return r;
}
__device__ __forceinline__ void ubf2(u32 v, float& a, float& b) {
    __nv_bfloat162 t = *reinterpret_cast<__nv_bfloat162*>(&v);
    a = __bfloat162float(t.x); b = __bfloat162float(t.y);
}
__device__ __forceinline__ void ldsm4(u32* r, u32 addr) {
    asm volatile("ldmatrix.sync.aligned.m8n8.x4.shared.b16 {%0,%1,%2,%3}, [%4];"
        : "=r"(r[0]), "=r"(r[1]), "=r"(r[2]), "=r"(r[3]) : "r"(addr));
}
__device__ __forceinline__ void mma16816(float* d, const u32* a, u32 b0, u32 b1) {
    asm volatile("mma.sync.aligned.m16n8k16.row.col.f32.bf16.bf16.f32 "
        "{%0,%1,%2,%3}, {%4,%5,%6,%7}, {%8,%9}, {%0,%1,%2,%3};"
        : "+f"(d[0]), "+f"(d[1]), "+f"(d[2]), "+f"(d[3])
        : "r"(a[0]), "r"(a[1]), "r"(a[2]), "r"(a[3]), "r"(b0), "r"(b1));
}

// Load [64][128] fp32 tile into staging, transpose-convert to bf16 hi/lo tiles
// [128 rows][64 cols], SW128 swizzled. Internal __syncthreads; caller syncs after.
__device__ __forceinline__ void xpose_cvt(const float* __restrict__ g, int c0g,
                                          float sc, char* sm,
                                          u32 dhi, u32 dlo, int tid) {
    float* stg = (float*)(sm + OFF_STG);
    #pragma unroll
    for (int f = tid; f < 2048; f += NTH) {
        int c = f >> 5, i4 = f & 31;
        *(float4*)&stg[c * 132 + i4 * 4] =
            *(const float4*)(g + (size_t)c * T_LEN + c0g + i4 * 4);
    }
    __syncthreads();
    int row = tid & 127;
    int c0  = (tid >> 7) * 32;
    u32 rowbase = (u32)row * 128;
    #pragma unroll
    for (int cc = 0; cc < 32; cc += 2) {
        float a = stg[(c0 + cc) * 132 + row] * sc;
        float b = stg[(c0 + cc + 1) * 132 + row] * sc;
        u32 h = pkbf(a, b);
        float fa, fb; ubf2(h, fa, fb);
        u32 l = pkbf(a - fa, b - fb);
        u32 off = SWZ(rowbase + (u32)(c0 + cc) * 2);
        *(u32*)(sm + dhi + off) = h;
        *(u32*)(sm + dlo + off) = l;
    }
}

// V convert (no transpose): gmem [c=64][s=128] -> two halves [64 rows][64 s cols].
__device__ __forceinline__ void v_cvt(const float* __restrict__ vg, int s0,
                                      char* sm, u32 dhi, u32 dlo, int tid) {
    #pragma unroll
    for (int f = tid; f < 2048; f += NTH) {
        int c = f >> 5, i4 = f & 31, s = i4 * 4;
        float4 v = *(const float4*)(vg + (size_t)c * T_LEN + s0 + s);
        u32 hA = pkbf(v.x, v.y), hB = pkbf(v.z, v.w);
        float fx, fy, fz, fw;
        ubf2(hA, fx, fy); ubf2(hB, fz, fw);
        u32 lA = pkbf(v.x - fx, v.y - fy);
        u32 lB = pkbf(v.z - fz, v.w - fw);
        u32 off = ((u32)(s >> 6) << 13) + SWZ((u32)c * 128 + (u32)(s & 63) * 2);
        *(uint2*)(sm + dhi + off) = make_uint2(hA, hB);
        *(uint2*)(sm + dlo + off) = make_uint2(lA, lB);
    }
}

__global__ __launch_bounds__(NTH, 1)
void qkv_attn_mma(const float* __restrict__ qkv,
                  const float* __restrict__ mask,
                  float* __restrict__ out)
{
    extern __shared__ char sm[];
    const u32 sb = smem_u32(sm);
    const int tid = threadIdx.x, wid = tid >> 5, lane = tid & 31;
    const int t0 = blockIdx.x * 128;
    const int bh = blockIdx.y;                   // b*16 + h
    const float* qg = qkv + (size_t)((bh >> 4) * 3072 + (bh & 15) * 64) * T_LEN;
    const float* kg = qg + (size_t)1024 * T_LEN;
    const float* vg = qg + (size_t)2048 * T_LEN;
    const float* mg = mask + (size_t)(bh & 7) * T_LEN;  // torch repeat: row = bh % 8

    const int tw = wid * 16;
    // ldmatrix per-lane addresses (byte offsets within a 128B-row tile)
    const u32 rowA = (u32)(tw + (lane & 15)) * 128 + ((u32)(lane >> 4) << 4);
    const u32 rowB = (u32)((lane & 7) + ((lane >> 4) << 3)) * 128
                   + (((u32)(lane >> 3) & 1) << 4);

    // Q once (scale 1/8 folded into split), then persistent A fragments
    xpose_cvt(qg, t0, 0.125f, sm, OFF_QHI, OFF_QLO, tid);
    __syncthreads();
    u32 ahi[4][4], alo[4][4];
    #pragma unroll
    for (int k = 0; k < 4; k++) {
        u32 off = SWZ(rowA + (u32)k * 32);
        ldsm4(ahi[k], sb + OFF_QHI + off);
        ldsm4(alo[k], sb + OFF_QLO + off);
    }

    // prologue: convert tiles for it=0 into buffer 0
    xpose_cvt(kg, 0, 1.0f, sm, OFF_K0, OFF_K0 + 16384, tid);
    v_cvt(vg, 0, sm, OFF_V0, OFF_V0 + 16384, tid);
    if (tid < 32)
        *(float4*)(sm + OFF_MASK + tid * 16) = *(const float4*)(mg + tid * 4);

    float oacc[8][4];
    #pragma unroll
    for (int i = 0; i < 8; i++)
        #pragma unroll
        for (int j = 0; j < 4; j++) oacc[i][j] = 0.0f;
    float lsum0 = 0.0f, lsum1 = 0.0f;

    for (int it = 0; it < 8; it++) {
        const int p = it & 1;
        const u32 kbuf = OFF_K0 + (u32)p * 32768;
        const u32 vbuf = OFF_V0 + (u32)p * 32768;
        __syncthreads();                         // tiles in buf p visible

        // ---- S = Qhi*Khi + Qhi*Klo + Qlo*Khi (issue only; results read later) ----
        float acc[16][4];
        #pragma unroll
        for (int i = 0; i < 16; i++)
            #pragma unroll
            for (int j = 0; j < 4; j++) acc[i][j] = 0.0f;

        #pragma unroll
        for (int g = 0; g < 8; g++) {
            #pragma unroll
            for (int k = 0; k < 4; k++) {
                u32 off = SWZ(rowB + (u32)g * 2048 + (u32)k * 32);
                u32 bh4[4], bl4[4];
                ldsm4(bh4, sb + kbuf + off);
                ldsm4(bl4, sb + kbuf + 16384 + off);
                mma16816(acc[2 * g],     ahi[k], bh4[0], bh4[1]);
                mma16816(acc[2 * g + 1], ahi[k], bh4[2], bh4[3]);
                mma16816(acc[2 * g],     ahi[k], bl4[0], bl4[1]);
                mma16816(acc[2 * g + 1], ahi[k], bl4[2], bl4[3]);
                mma16816(acc[2 * g],     alo[k], bh4[0], bh4[1]);
                mma16816(acc[2 * g + 1], alo[k], bh4[2], bh4[3]);
            }
        }

        // ---- overlap: convert NEXT iteration's K/V into buf 1-p while the
        //      S HMMAs drain through the tensor pipe ----
        if (it < 7) {
            const int sn = (it + 1) * 128;
            const u32 kn = OFF_K0 + (u32)(1 - p) * 32768;
            const u32 vn = OFF_V0 + (u32)(1 - p) * 32768;
            xpose_cvt(kg, sn, 1.0f, sm, kn, kn + 16384, tid);
            v_cvt(vg, sn, sm, vn, vn + 16384, tid);
            if (tid < 32)
                *(float4*)(sm + OFF_MASK + 512 * (1 - p) + tid * 16) =
                    *(const float4*)(mg + sn + tid * 4);
        }

        // ---- softmax (no max-sub: |S*m| <= ~6) + in-register bf16 hi/lo split ----
        u32 phi[8][4], plo[8][4];
        const float* smk = (const float*)(sm + OFF_MASK + 512 * p);
        #pragma unroll
        for (int j = 0; j < 16; j++) {
            float2 mm = *(const float2*)(smk + 8 * j + 2 * (lane & 3));
            float e0 = __expf(acc[j][0] * mm.x);
            float e1 = __expf(acc[j][1] * mm.y);
            float e2 = __expf(acc[j][2] * mm.x);
            float e3 = __expf(acc[j][3] * mm.y);
            lsum0 += e0 + e1;
            lsum1 += e2 + e3;
            u32 h01 = pkbf(e0, e1), h23 = pkbf(e2, e3);
            float f0, f1, f2, f3;
            ubf2(h01, f0, f1); ubf2(h23, f2, f3);
            u32 l01 = pkbf(e0 - f0, e1 - f1), l23 = pkbf(e2 - f2, e3 - f3);
            int q = j >> 1, o = (j & 1) * 2;
            phi[q][o] = h01; phi[q][o + 1] = h23;
            plo[q][o] = l01; plo[q][o + 1] = l23;
        }

        // ---- O += Phi*Vhi + Phi*Vlo + Plo*Vhi  (k = s, 8 k16-steps) ----
        #pragma unroll
        for (int q = 0; q < 8; q++) {
            const u32 kb = (u32)(q & 3) * 32;
            const u32 hoff = ((u32)(q >> 2) << 13);
            #pragma unroll
            for (int gp = 0; gp < 4; gp++) {
                u32 off = hoff + SWZ(rowB + (u32)gp * 2048 + kb);
                u32 vh4[4], vl4[4];
                ldsm4(vh4, sb + vbuf + off);
                ldsm4(vl4, sb + vbuf + 16384 + off);
                mma16816(oacc[2 * gp],     phi[q], vh4[0], vh4[1]);
                mma16816(oacc[2 * gp + 1], phi[q], vh4[2], vh4[3]);
                mma16816(oacc[2 * gp],     phi[q], vl4[0], vl4[1]);
                mma16816(oacc[2 * gp + 1], phi[q], vl4[2], vl4[3]);
                mma16816(oacc[2 * gp],     plo[q], vh4[0], vh4[1]);
                mma16816(oacc[2 * gp + 1], plo[q], vh4[2], vh4[3]);
            }
        }
    }

    // ---- epilogue: reduce l across quad, normalize, stage transpose, write ----
    __syncthreads();                             // staging free
    lsum0 += __shfl_xor_sync(0xffffffffu, lsum0, 1);
    lsum0 += __shfl_xor_sync(0xffffffffu, lsum0, 2);
    lsum1 += __shfl_xor_sync(0xffffffffu, lsum1, 1);
    lsum1 += __shfl_xor_sync(0xffffffffu, lsum1, 2);
    const float inv0 = 1.0f / lsum0, inv1 = 1.0f / lsum1;

    float* stg = (float*)(sm + OFF_STG);         // [c=64][t pitch 132]
    const int r = tw + (lane >> 2);
    #pragma unroll
    for (int j = 0; j < 8; j++) {
        int c0 = 8 * j + 2 * (lane & 3);
        stg[c0 * 132 + r]           = oacc[j][0] * inv0;
        stg[(c0 + 1) * 132 + r]     = oacc[j][1] * inv0;
        stg[c0 * 132 + r + 8]       = oacc[j][2] * inv1;
        stg[(c0 + 1) * 132 + r + 8] = oacc[j][3] * inv1;
    }
    __syncthreads();
    float* ob = out + (size_t)bh * 64 * T_LEN + t0;
    #pragma unroll
    for (int f = tid; f < 64 * 32; f += NTH) {
        int c = f >> 5, t4 = (f & 31) * 4;
        *(float4*)(ob + (size_t)c * T_LEN + t4) = *(float4*)(stg + c * 132 + t4);
    }
}

extern "C" void kernel_launch(void* const* d_in, const int* in_sizes, int n_in,
                              void* d_out, int out_size)
{
    const float* qkv  = (const float*)d_in[0];
    const float* mask = (const float*)d_in[1];
    float* out        = (float*)d_out;
    (void)in_sizes; (void)n_in; (void)out_size;

    cudaFuncSetAttribute(qkv_attn_mma,
                         cudaFuncAttributeMaxDynamicSharedMemorySize, SMEM_BYTES);
    dim3 grid(T_LEN / 128, 8 * 16);
    qkv_attn_mma<<<grid, NTH, SMEM_BYTES>>>(qkv, mask, out);
}